// round 3
// baseline (speedup 1.0000x reference)
#include <cuda_runtime.h>
#include <mma.h>
#include <cstdint>

using namespace nvcuda;

#define DIN 128
#define DOUT 128
#define NEG_SLOPE 0.2f
#define MAX_N 50048
#define MAX_EN 860000   // E + N with slack

// ---------------- scratch (no allocations allowed) ----------------
__device__ float g_xw[(size_t)MAX_N * DOUT];   // x @ W
__device__ float g_asrc[MAX_N];
__device__ float g_adst[MAX_N];
__device__ int   g_deg[MAX_N];                 // in-degree histogram
__device__ int   g_start[MAX_N + 1];           // CSR row offsets (by dst)
__device__ int   g_cursor[MAX_N];              // scatter cursors
__device__ int   g_csr_src[MAX_EN];            // src node per CSR slot
__device__ float g_ev[MAX_EN];                 // leaky-relu logit per CSR slot
__device__ int   g_is64;

// ---------------- kernels ----------------

// Detect int64 vs int32 edge_index (reads 64 bytes, safe either way).
__global__ void k_detect(const long long* ei, int n) {
    bool ok = true;
#pragma unroll
    for (int i = 0; i < 8; i++) {
        long long v = ei[i];
        if (v < 0 || v >= (long long)n) ok = false;
    }
    g_is64 = ok ? 1 : 0;
}

__global__ void k_zero_deg(int n) {
    int i = blockIdx.x * blockDim.x + threadIdx.x;
    if (i < n) g_deg[i] = 0;
}

// Histogram of destinations (incl. self loops appended at the end).
__global__ void k_hist(const void* ei, int E, int n) {
    int i = blockIdx.x * blockDim.x + threadIdx.x;
    if (i >= E + n) return;
    int d;
    if (i >= E) d = i - E;
    else if (g_is64) d = (int)((const long long*)ei)[i + E];
    else             d = ((const int*)ei)[i + E];
    atomicAdd(&g_deg[d], 1);
}

// ---------------- GEMM: xw = x @ W via 3xTF32 tensor-core mma ----------------
// Block tile 128x128, BK=32, 256 threads = 8 warps (4x2), warp tile 32x64.
#define LDA 40
#define LDB 136

__global__ __launch_bounds__(256, 2) void k_gemm(const float* __restrict__ x,
                                                 const float* __restrict__ W,
                                                 int n) {
    __shared__ float As[128][LDA];
    __shared__ float Bs[32][LDB];
    const int tid = threadIdx.x;
    const int warp = tid >> 5;
    const int wm = (warp & 3) * 32;      // warp row offset in block tile
    const int wn = (warp >> 2) * 64;     // warp col offset in block tile
    const int row0 = blockIdx.x * 128;

    wmma::fragment<wmma::accumulator, 16, 16, 8, float> acc[2][4];
#pragma unroll
    for (int i = 0; i < 2; i++)
#pragma unroll
        for (int j = 0; j < 4; j++) wmma::fill_fragment(acc[i][j], 0.0f);

    for (int k0 = 0; k0 < DIN; k0 += 32) {
        // A tile 128x32: 1024 float4, 4 per thread
#pragma unroll
        for (int h = 0; h < 4; h++) {
            int f = tid + h * 256;
            int r = f >> 3, kq = (f & 7) * 4;
            int row = row0 + r; if (row >= n) row = n - 1;
            float4 v = *(const float4*)(x + (size_t)row * DIN + k0 + kq);
            As[r][kq + 0] = v.x; As[r][kq + 1] = v.y;
            As[r][kq + 2] = v.z; As[r][kq + 3] = v.w;
        }
        // B tile 32x128: 1024 float4, 4 per thread
#pragma unroll
        for (int h = 0; h < 4; h++) {
            int f = tid + h * 256;
            int kr = f >> 5, c = (f & 31) * 4;
            float4 v = *(const float4*)(W + (size_t)(k0 + kr) * DOUT + c);
            Bs[kr][c + 0] = v.x; Bs[kr][c + 1] = v.y;
            Bs[kr][c + 2] = v.z; Bs[kr][c + 3] = v.w;
        }
        __syncthreads();

#pragma unroll
        for (int ks = 0; ks < 32; ks += 8) {
            wmma::fragment<wmma::matrix_a, 16, 16, 8, wmma::precision::tf32, wmma::row_major> a_hi[2], a_lo[2];
#pragma unroll
            for (int i = 0; i < 2; i++) {
                wmma::fragment<wmma::matrix_a, 16, 16, 8, wmma::precision::tf32, wmma::row_major> af;
                wmma::load_matrix_sync(af, &As[wm + i * 16][ks], LDA);
#pragma unroll
                for (int e = 0; e < af.num_elements; e++) {
                    float v = af.x[e];
                    float hi = wmma::__float_to_tf32(v);
                    a_hi[i].x[e] = hi;
                    a_lo[i].x[e] = wmma::__float_to_tf32(v - hi);
                }
            }
#pragma unroll
            for (int j = 0; j < 4; j++) {
                wmma::fragment<wmma::matrix_b, 16, 16, 8, wmma::precision::tf32, wmma::row_major> b_hi, b_lo;
                {
                    wmma::fragment<wmma::matrix_b, 16, 16, 8, wmma::precision::tf32, wmma::row_major> bf;
                    wmma::load_matrix_sync(bf, &Bs[ks][wn + j * 16], LDB);
#pragma unroll
                    for (int e = 0; e < bf.num_elements; e++) {
                        float v = bf.x[e];
                        float hi = wmma::__float_to_tf32(v);
                        b_hi.x[e] = hi;
                        b_lo.x[e] = wmma::__float_to_tf32(v - hi);
                    }
                }
#pragma unroll
                for (int i = 0; i < 2; i++) {
                    wmma::mma_sync(acc[i][j], a_lo[i], b_hi, acc[i][j]);
                    wmma::mma_sync(acc[i][j], a_hi[i], b_lo, acc[i][j]);
                    wmma::mma_sync(acc[i][j], a_hi[i], b_hi, acc[i][j]);
                }
            }
        }
        __syncthreads();
    }

    // store (rows beyond n land in the MAX_N slack, never read)
#pragma unroll
    for (int i = 0; i < 2; i++)
#pragma unroll
        for (int j = 0; j < 4; j++)
            wmma::store_matrix_sync(g_xw + (size_t)(row0 + wm + i * 16) * DOUT + wn + j * 16,
                                    acc[i][j], DOUT, wmma::mem_row_major);
}

// Per-node attention logits: one warp per row.
__global__ void k_rowdot(const float* __restrict__ att_src,
                         const float* __restrict__ att_dst, int n) {
    int gtid = blockIdx.x * blockDim.x + threadIdx.x;
    int w = gtid >> 5, lane = gtid & 31;
    if (w >= n) return;
    float4 v = ((const float4*)(g_xw + (size_t)w * DOUT))[lane];
    float4 s = ((const float4*)att_src)[lane];
    float4 d = ((const float4*)att_dst)[lane];
    float ps = v.x * s.x + v.y * s.y + v.z * s.z + v.w * s.w;
    float pd = v.x * d.x + v.y * d.y + v.z * d.z + v.w * d.w;
#pragma unroll
    for (int o = 16; o; o >>= 1) {
        ps += __shfl_xor_sync(0xffffffffu, ps, o);
        pd += __shfl_xor_sync(0xffffffffu, pd, o);
    }
    if (lane == 0) { g_asrc[w] = ps; g_adst[w] = pd; }
}

// Single-block exclusive scan of g_deg -> g_start/g_cursor (4 elems/thread).
__global__ __launch_bounds__(1024) void k_scan(int n) {
    __shared__ int warp_tot[32];
    __shared__ int s_carry;
    int tid = threadIdx.x, lane = tid & 31, wid = tid >> 5;
    if (tid == 0) s_carry = 0;
    __syncthreads();
    for (int base = 0; base < n; base += 4096) {
        int i0 = base + tid * 4;
        int4 v = make_int4(0, 0, 0, 0);
        if (i0 + 3 < n) v = *(const int4*)&g_deg[i0];
        else {
            if (i0 + 0 < n) v.x = g_deg[i0 + 0];
            if (i0 + 1 < n) v.y = g_deg[i0 + 1];
            if (i0 + 2 < n) v.z = g_deg[i0 + 2];
            if (i0 + 3 < n) v.w = g_deg[i0 + 3];
        }
        int s = v.x + v.y + v.z + v.w;
        int sc = s;
#pragma unroll
        for (int off = 1; off < 32; off <<= 1) {
            int t = __shfl_up_sync(0xffffffffu, sc, off);
            if (lane >= off) sc += t;
        }
        if (lane == 31) warp_tot[wid] = sc;
        __syncthreads();
        if (wid == 0) {
            int wv = warp_tot[lane];
            int wsc = wv;
#pragma unroll
            for (int off = 1; off < 32; off <<= 1) {
                int t = __shfl_up_sync(0xffffffffu, wsc, off);
                if (lane >= off) wsc += t;
            }
            warp_tot[lane] = wsc - wv;   // exclusive
        }
        __syncthreads();
        int excl = s_carry + warp_tot[wid] + (sc - s);
        int a0 = excl, a1 = a0 + v.x, a2 = a1 + v.y, a3 = a2 + v.z;
        if (i0 + 0 < n) { g_start[i0 + 0] = a0; g_cursor[i0 + 0] = a0; }
        if (i0 + 1 < n) { g_start[i0 + 1] = a1; g_cursor[i0 + 1] = a1; }
        if (i0 + 2 < n) { g_start[i0 + 2] = a2; g_cursor[i0 + 2] = a2; }
        if (i0 + 3 < n) { g_start[i0 + 3] = a3; g_cursor[i0 + 3] = a3; }
        __syncthreads();
        if (tid == 1023) s_carry = excl + s;
        __syncthreads();
    }
    if (tid == 0) g_start[n] = s_carry;
}

// Scatter edges into CSR order + fused leaky-relu logit.
__global__ void k_scatter(const void* ei, int E, int n) {
    int i = blockIdx.x * blockDim.x + threadIdx.x;
    if (i >= E + n) return;
    int s, d;
    if (i >= E) { s = d = i - E; }
    else if (g_is64) {
        const long long* p = (const long long*)ei;
        s = (int)p[i]; d = (int)p[i + E];
    } else {
        const int* p = (const int*)ei;
        s = p[i]; d = p[i + E];
    }
    float e = g_asrc[s] + g_adst[d];
    e = (e > 0.0f) ? e : NEG_SLOPE * e;
    int pos = atomicAdd(&g_cursor[d], 1);
    g_csr_src[pos] = s;
    g_ev[pos] = e;
}

// Fused GAT gather: segment softmax + weighted aggregate + bias + ELU.
// One warp per destination node, float4 per lane (128 cols).
__global__ __launch_bounds__(256) void k_gat(float* __restrict__ out,
                                             const float* __restrict__ bias,
                                             int n) {
    int gtid = blockIdx.x * blockDim.x + threadIdx.x;
    int w = gtid >> 5, lane = gtid & 31;
    if (w >= n) return;
    int s0 = g_start[w], s1 = g_start[w + 1];

    // segment max
    float m = -1e30f;
    for (int j = s0 + lane; j < s1; j += 32) m = fmaxf(m, g_ev[j]);
#pragma unroll
    for (int off = 16; off; off >>= 1)
        m = fmaxf(m, __shfl_xor_sync(0xffffffffu, m, off));

    // softmax + weighted aggregate (software-pipelined src/ev prefetch)
    float4 acc = make_float4(0.f, 0.f, 0.f, 0.f);
    float denom = 0.f;
    float ev_n = 0.f; int src_n = 0;
    if (s0 < s1) { ev_n = g_ev[s0]; src_n = g_csr_src[s0]; }
    for (int j = s0; j < s1; j++) {
        float ev_c = ev_n; int src_c = src_n;
        if (j + 1 < s1) { ev_n = g_ev[j + 1]; src_n = g_csr_src[j + 1]; }
        float4 v = ((const float4*)(g_xw + (size_t)src_c * DOUT))[lane];
        float alpha = __expf(ev_c - m);
        denom += alpha;
        acc.x += alpha * v.x; acc.y += alpha * v.y;
        acc.z += alpha * v.z; acc.w += alpha * v.w;
    }

    float r = 1.0f / denom;
    float4 b = ((const float4*)bias)[lane];
    float4 o;
    o.x = acc.x * r + b.x; o.y = acc.y * r + b.y;
    o.z = acc.z * r + b.z; o.w = acc.w * r + b.w;
    o.x = (o.x > 0.f) ? o.x : expm1f(o.x);
    o.y = (o.y > 0.f) ? o.y : expm1f(o.y);
    o.z = (o.z > 0.f) ? o.z : expm1f(o.z);
    o.w = (o.w > 0.f) ? o.w : expm1f(o.w);
    ((float4*)(out + (size_t)w * DOUT))[lane] = o;
}

// ---------------- launch ----------------
extern "C" void kernel_launch(void* const* d_in, const int* in_sizes, int n_in,
                              void* d_out, int out_size) {
    const float* x       = (const float*)d_in[0];
    const void*  ei      = d_in[1];
    const float* W       = (const float*)d_in[2];
    const float* att_src = (const float*)d_in[3];
    const float* att_dst = (const float*)d_in[4];
    const float* bias    = (const float*)d_in[5];
    float* out = (float*)d_out;

    const int n  = in_sizes[0] / DIN;
    const int E  = in_sizes[1] / 2;
    const int EN = E + n;

    k_detect<<<1, 1>>>((const long long*)ei, n);
    k_zero_deg<<<(n + 255) / 256, 256>>>(n);
    k_hist<<<(EN + 255) / 256, 256>>>(ei, E, n);
    k_gemm<<<(n + 127) / 128, 256>>>(x, W, n);
    k_rowdot<<<(n * 32 + 255) / 256, 256>>>(att_src, att_dst, n);
    k_scan<<<1, 1024>>>(n);
    k_scatter<<<(EN + 255) / 256, 256>>>(ei, E, n);
    k_gat<<<(n * 32 + 255) / 256, 256>>>(out, bias, n);
}